// round 8
// baseline (speedup 1.0000x reference)
#include <cuda_runtime.h>
#include <cuda_bf16.h>
#include <cstdint>

// Problem dims (fixed)
#define BB 4
#define TT 2048
#define CC 1024
#define HH 16
#define DD 64
#define FF 4096
#define MM (BB*TT)   // 8192 rows

// ===================== PTX helpers (sm_100-safe: mma.sync/ldmatrix/cp.async) =
__device__ __forceinline__ uint32_t smem_to_u32(const void* p) {
    uint32_t a;
    asm("{ .reg .u64 t; cvta.to.shared.u64 t, %1; cvt.u32.u64 %0, t; }"
        : "=r"(a) : "l"(p));
    return a;
}
#define CP_ASYNC16(dst, src) \
    asm volatile("cp.async.cg.shared.global [%0], [%1], 16;" :: "r"(dst), "l"(src))
#define CP_COMMIT() asm volatile("cp.async.commit_group;" ::: "memory")
#define CP_WAIT(n)  asm volatile("cp.async.wait_group %0;" :: "n"(n) : "memory")

__device__ __forceinline__ void ldsm4(uint32_t* r, uint32_t addr) {
    asm volatile("ldmatrix.sync.aligned.m8n8.x4.shared.b16 {%0,%1,%2,%3}, [%4];"
        : "=r"(r[0]), "=r"(r[1]), "=r"(r[2]), "=r"(r[3]) : "r"(addr));
}
__device__ __forceinline__ void mma16816(float* c, const uint32_t* a,
                                         uint32_t b0, uint32_t b1) {
    asm volatile(
        "mma.sync.aligned.m16n8k16.row.col.f32.bf16.bf16.f32 "
        "{%0,%1,%2,%3}, {%4,%5,%6,%7}, {%8,%9}, {%0,%1,%2,%3};"
        : "+f"(c[0]), "+f"(c[1]), "+f"(c[2]), "+f"(c[3])
        : "r"(a[0]), "r"(a[1]), "r"(a[2]), "r"(a[3]), "r"(b0), "r"(b1));
}

// ===================== scratch (device globals) =============================
__device__ __nv_bfloat16 g_hh [MM*CC], g_hl [MM*CC];      // LN out hi/lo
__device__ float         g_q  [MM*CC], g_k  [MM*CC], g_v[MM*CC];
__device__ __nv_bfloat16 g_ath[MM*CC], g_atl[MM*CC];      // attention out hi/lo
__device__ float         g_x1 [MM*CC];
__device__ __nv_bfloat16 g_ffh[(size_t)MM*FF], g_ffl[(size_t)MM*FF];
__device__ __nv_bfloat16 g_wqh[CC*CC], g_wql[CC*CC];
__device__ __nv_bfloat16 g_wkh[CC*CC], g_wkl[CC*CC];
__device__ __nv_bfloat16 g_wvh[CC*CC], g_wvl[CC*CC];
__device__ __nv_bfloat16 g_woh[CC*CC], g_wol[CC*CC];
__device__ __nv_bfloat16 g_w1h[(size_t)CC*FF], g_w1l[(size_t)CC*FF];
__device__ __nv_bfloat16 g_w2h[(size_t)FF*CC], g_w2l[(size_t)FF*CC];

// split fp32 -> (hi, lo) bf16 pair, 2 at a time
__device__ __forceinline__ void split2_store(float x0, float x1,
                                             __nv_bfloat16* hp, __nv_bfloat16* lp) {
    __nv_bfloat16 h0 = __float2bfloat16_rn(x0), h1 = __float2bfloat16_rn(x1);
    *(__nv_bfloat162*)hp = __halves2bfloat162(h0, h1);
    float l0 = x0 - __bfloat162float(h0), l1 = x1 - __bfloat162float(h1);
    *(__nv_bfloat162*)lp = __halves2bfloat162(__float2bfloat16_rn(l0),
                                              __float2bfloat16_rn(l1));
}
__device__ __forceinline__ void split4_store(float x0, float x1, float x2, float x3,
                                             __nv_bfloat16* hp, __nv_bfloat16* lp) {
    split2_store(x0, x1, hp, lp);
    split2_store(x2, x3, hp + 2, lp + 2);
}

// ===================== weight transpose + split =============================
// W [K, N] fp32 -> Th/Tl [N, K] bf16 (GEMM B operand is K-major per n-row)
__global__ void __launch_bounds__(256) tsplit_k(const float* __restrict__ W,
                                                __nv_bfloat16* __restrict__ Th,
                                                __nv_bfloat16* __restrict__ Tl,
                                                int K, int N)
{
    __shared__ float t[32][33];
    int n0 = blockIdx.x * 32, k0 = blockIdx.y * 32;
    int tx = threadIdx.x & 31, ty = threadIdx.x >> 5;   // 32 x 8
    #pragma unroll
    for (int i = 0; i < 4; i++)
        t[ty + 8*i][tx] = W[(size_t)(k0 + ty + 8*i) * N + n0 + tx];
    __syncthreads();
    #pragma unroll
    for (int i = 0; i < 4; i++) {
        float v = t[tx][ty + 8*i];
        size_t o = (size_t)(n0 + ty + 8*i) * K + k0 + tx;
        __nv_bfloat16 h = __float2bfloat16_rn(v);
        Th[o] = h;
        Tl[o] = __float2bfloat16_rn(v - __bfloat162float(h));
    }
}

// ===================== LayerNorm -> bf16 hi/lo ==============================
__global__ void __launch_bounds__(256) ln_k(const float* __restrict__ x,
                                            const float* __restrict__ gam,
                                            const float* __restrict__ bet,
                                            __nv_bfloat16* __restrict__ oh,
                                            __nv_bfloat16* __restrict__ ol)
{
    int row = blockIdx.x;
    int tid = threadIdx.x;
    const float4* xr = (const float4*)(x + (size_t)row * CC);
    float4 v = xr[tid];
    float s  = v.x + v.y + v.z + v.w;
    float sq = v.x*v.x + v.y*v.y + v.z*v.z + v.w*v.w;
    #pragma unroll
    for (int o = 16; o > 0; o >>= 1) {
        s  += __shfl_xor_sync(0xffffffffu, s,  o);
        sq += __shfl_xor_sync(0xffffffffu, sq, o);
    }
    __shared__ float rs[8], rq[8];
    int w = tid >> 5, lane = tid & 31;
    if (lane == 0) { rs[w] = s; rq[w] = sq; }
    __syncthreads();
    s = 0.f; sq = 0.f;
    #pragma unroll
    for (int i = 0; i < 8; i++) { s += rs[i]; sq += rq[i]; }
    float mu  = s * (1.f / CC);
    float inv = rsqrtf(sq * (1.f / CC) - mu * mu + 1e-5f);
    float4 g4 = ((const float4*)gam)[tid];
    float4 b4 = ((const float4*)bet)[tid];
    float r0 = (v.x - mu) * inv * g4.x + b4.x;
    float r1 = (v.y - mu) * inv * g4.y + b4.y;
    float r2 = (v.z - mu) * inv * g4.z + b4.z;
    float r3 = (v.w - mu) * inv * g4.w + b4.w;
    size_t base = (size_t)row * CC + tid * 4;
    split4_store(r0, r1, r2, r3, oh + base, ol + base);
}

// ===================== mma.sync GEMM ========================================
// C[M,N] = A[M,K] @ Bt[N,K]^T via 3-term bf16 split (logical K' = 3K):
//   term 0: Ah*Bh, term 1: Al*Bh, term 2: Ah*Bl — fp32 accum.
// 128x128 block, 8 warps (2M x 4N), 64x32 per warp, m16n8k16 frags.
// BK=32 bf16 per stage, cp.async double buffer, smem rows padded to 40 bf16
// (granule 5*row+c mod 8 is a permutation -> conflict-free ldmatrix).
// EP: 0 = fp32 store; 1 = fp32 store of (D+bias+res); 2 = bf16 hi/lo split
//     store of relu(D+bias).
template<int EP>
__global__ void __launch_bounds__(256) gemm_mma(
    const __nv_bfloat16* __restrict__ Ah, const __nv_bfloat16* __restrict__ Al,
    const __nv_bfloat16* __restrict__ Bh, const __nv_bfloat16* __restrict__ Bl,
    const float* __restrict__ bias, const float* __restrict__ res,
    float* __restrict__ Cf,
    __nv_bfloat16* __restrict__ Chi, __nv_bfloat16* __restrict__ Clo,
    int M, int N, int K)
{
    __shared__ __nv_bfloat16 As[2][128][40];
    __shared__ __nv_bfloat16 Bs[2][128][40];

    const int tid  = threadIdx.x;
    const int wid  = tid >> 5;
    const int lane = tid & 31;
    const int bm = blockIdx.y * 128, bn = blockIdx.x * 128;
    const int wm = wid & 1;          // 0..1 -> 64-row slice
    const int wn = wid >> 1;         // 0..3 -> 32-col slice

    const int kc = K >> 5;           // 32-wide chunks per term
    const int kt = 3 * kc;           // total stages

    // loader mapping: thread -> (row = tid/2, 32-byte half-row)
    const int lrow = tid >> 1;
    const int lc   = (tid & 1) * 16;                    // bf16 col offset

    float acc[4][4][4];
    #pragma unroll
    for (int i = 0; i < 4; i++)
        #pragma unroll
        for (int j = 0; j < 4; j++)
            #pragma unroll
            for (int q = 0; q < 4; q++) acc[i][j][q] = 0.f;

    // ---- stage issue helper (inlined manually via lambda) ----
    auto issue = [&](int t, int buf) {
        int term = (t >= 2*kc) ? 2 : (t >= kc ? 1 : 0);
        int koff = (t - term * kc) * 32;
        const __nv_bfloat16* pa = (term == 1) ? Al : Ah;
        const __nv_bfloat16* pb = (term == 2) ? Bl : Bh;
        const __nv_bfloat16* ga = pa + (size_t)(bm + lrow) * K + koff + lc;
        const __nv_bfloat16* gb = pb + (size_t)(bn + lrow) * K + koff + lc;
        uint32_t da = smem_to_u32(&As[buf][lrow][lc]);
        uint32_t db = smem_to_u32(&Bs[buf][lrow][lc]);
        CP_ASYNC16(da,      ga);
        CP_ASYNC16(da + 16, ga + 8);
        CP_ASYNC16(db,      gb);
        CP_ASYNC16(db + 16, gb + 8);
    };

    issue(0, 0);
    CP_COMMIT();

    for (int t = 0; t < kt; t++) {
        const int buf = t & 1;
        if (t + 1 < kt) {
            issue(t + 1, buf ^ 1);
            CP_COMMIT();
            CP_WAIT(1);
        } else {
            CP_WAIT(0);
        }
        __syncthreads();

        // ---- compute stage: 2 k-steps of 16 ----
        #pragma unroll
        for (int ks = 0; ks < 2; ks++) {
            const int kb = ks * 16 + (lane >> 4) * 8;   // ldmatrix col
            uint32_t a[4][4];
            #pragma unroll
            for (int mf = 0; mf < 4; mf++) {
                uint32_t addr = smem_to_u32(&As[buf][wm*64 + mf*16 + (lane & 15)][kb]);
                ldsm4(a[mf], addr);
            }
            uint32_t b[2][4];
            #pragma unroll
            for (int bf = 0; bf < 2; bf++) {
                uint32_t addr = smem_to_u32(&Bs[buf][wn*32 + bf*16 + (lane & 15)][kb]);
                ldsm4(b[bf], addr);
            }
            #pragma unroll
            for (int mf = 0; mf < 4; mf++) {
                #pragma unroll
                for (int nf = 0; nf < 4; nf++) {
                    uint32_t b0 = b[nf >> 1][(nf & 1) ? 1 : 0];
                    uint32_t b1 = b[nf >> 1][(nf & 1) ? 3 : 2];
                    mma16816(acc[mf][nf], a[mf], b0, b1);
                }
            }
        }
        __syncthreads();
    }

    // ---- epilogue ----
    const int r0 = bm + wm * 64 + (lane >> 2);
    const int c0 = bn + wn * 32 + (lane & 3) * 2;
    #pragma unroll
    for (int mf = 0; mf < 4; mf++) {
        #pragma unroll
        for (int nf = 0; nf < 4; nf++) {
            int row = r0 + mf * 16;
            int col = c0 + nf * 8;
            #pragma unroll
            for (int half = 0; half < 2; half++) {       // rows row, row+8
                int rr = row + half * 8;
                float v0 = acc[mf][nf][half*2 + 0];
                float v1 = acc[mf][nf][half*2 + 1];
                size_t o = (size_t)rr * N + col;
                if (EP >= 1) {
                    float2 bb = *(const float2*)(bias + col);
                    v0 += bb.x; v1 += bb.y;
                }
                if (EP == 2) {
                    v0 = fmaxf(v0, 0.f); v1 = fmaxf(v1, 0.f);
                    split2_store(v0, v1, Chi + o, Clo + o);
                } else {
                    if (EP == 1) {
                        float2 rv = *(const float2*)(res + o);
                        v0 += rv.x; v1 += rv.y;
                    }
                    *(float2*)(Cf + o) = make_float2(v0, v1);
                }
            }
        }
    }
}

// ===================== Flash attention (causal, fp32 -> bf16 hi/lo out) =====
__global__ void __launch_bounds__(128) flash_k(const float* __restrict__ Q,
                                               const float* __restrict__ Kg,
                                               const float* __restrict__ Vg,
                                               __nv_bfloat16* __restrict__ Oh,
                                               __nv_bfloat16* __restrict__ Ol)
{
    __shared__ float q_s[128][68];
    __shared__ float k_s[16][64];
    __shared__ float v_s[16][64];
    int qt  = blockIdx.x;
    int bh  = blockIdx.y;
    int b   = bh >> 4, h = bh & 15;
    int tid = threadIdx.x;

    const float* Qb  = Q  + ((size_t)(b * TT + qt * 128)) * CC + h * DD;
    const float* Kb0 = Kg + ((size_t)b * TT) * CC + h * DD;
    const float* Vb0 = Vg + ((size_t)b * TT) * CC + h * DD;

    for (int idx = tid; idx < 128 * 16; idx += 128) {
        int r = idx >> 4, d4 = idx & 15;
        float4 t = *(const float4*)(Qb + (size_t)r * CC + d4 * 4);
        t.x *= 0.03125f; t.y *= 0.03125f; t.z *= 0.03125f; t.w *= 0.03125f;
        *(float4*)&q_s[r][d4 * 4] = t;
    }

    int qrow = qt * 128 + tid;
    float m = -1e30f, l = 0.f;
    float o[64];
    #pragma unroll
    for (int d = 0; d < 64; d++) o[d] = 0.f;

    int kend = qt * 128 + 128;
    for (int k0 = 0; k0 < kend; k0 += 16) {
        __syncthreads();
        for (int idx = tid; idx < 16 * 16; idx += 128) {
            int r = idx >> 4, d4 = idx & 15;
            *(float4*)&k_s[r][d4*4] = *(const float4*)(Kb0 + (size_t)(k0 + r) * CC + d4 * 4);
            *(float4*)&v_s[r][d4*4] = *(const float4*)(Vb0 + (size_t)(k0 + r) * CC + d4 * 4);
        }
        __syncthreads();

        float s[16];
        #pragma unroll
        for (int j = 0; j < 16; j++) s[j] = 0.f;
        #pragma unroll 4
        for (int d4 = 0; d4 < 16; d4++) {
            float4 q4 = *(const float4*)&q_s[tid][d4 * 4];
            #pragma unroll
            for (int j = 0; j < 16; j++) {
                float4 k4 = *(const float4*)&k_s[j][d4 * 4];
                s[j] += q4.x*k4.x + q4.y*k4.y + q4.z*k4.z + q4.w*k4.w;
            }
        }
        if (k0 + 15 > qrow) {
            #pragma unroll
            for (int j = 0; j < 16; j++)
                if (k0 + j > qrow) s[j] = -1e30f;
        }
        float mt = m;
        #pragma unroll
        for (int j = 0; j < 16; j++) mt = fmaxf(mt, s[j]);
        float alpha = __expf(m - mt);
        m = mt;
        l *= alpha;
        #pragma unroll
        for (int d = 0; d < 64; d++) o[d] *= alpha;
        #pragma unroll 4
        for (int j = 0; j < 16; j++) {
            float p = __expf(s[j] - m);
            l += p;
            #pragma unroll
            for (int d4 = 0; d4 < 16; d4++) {
                float4 v4 = *(const float4*)&v_s[j][d4 * 4];
                o[d4*4+0] += p * v4.x;
                o[d4*4+1] += p * v4.y;
                o[d4*4+2] += p * v4.z;
                o[d4*4+3] += p * v4.w;
            }
        }
    }
    float inv = 1.f / l;
    size_t base = ((size_t)(b * TT + qrow)) * CC + h * DD;
    #pragma unroll
    for (int d4 = 0; d4 < 16; d4++) {
        split4_store(o[d4*4+0]*inv, o[d4*4+1]*inv, o[d4*4+2]*inv, o[d4*4+3]*inv,
                     Oh + base + d4*4, Ol + base + d4*4);
    }
}

// ===================== launch ===============================================
extern "C" void kernel_launch(void* const* d_in, const int* in_sizes, int n_in,
                              void* d_out, int out_size)
{
    const float* x     = (const float*)d_in[0];
    const float* Wq    = (const float*)d_in[1];
    const float* Wk    = (const float*)d_in[2];
    const float* Wv    = (const float*)d_in[3];
    const float* Wo    = (const float*)d_in[4];
    const float* bo    = (const float*)d_in[5];
    const float* W1    = (const float*)d_in[6];
    const float* b1    = (const float*)d_in[7];
    const float* W2    = (const float*)d_in[8];
    const float* b2    = (const float*)d_in[9];
    const float* ln1g  = (const float*)d_in[10];
    const float* ln1b  = (const float*)d_in[11];
    const float* ln2g  = (const float*)d_in[12];
    const float* ln2b  = (const float*)d_in[13];
    float* out = (float*)d_out;

    __nv_bfloat16 *hh, *hl, *ath, *atl, *ffh, *ffl;
    __nv_bfloat16 *wqh, *wql, *wkh, *wkl, *wvh, *wvl, *woh, *wol, *w1h, *w1l, *w2h, *w2l;
    float *q, *k, *v, *x1;
    cudaGetSymbolAddress((void**)&hh,  g_hh);  cudaGetSymbolAddress((void**)&hl,  g_hl);
    cudaGetSymbolAddress((void**)&q,   g_q);   cudaGetSymbolAddress((void**)&k,   g_k);
    cudaGetSymbolAddress((void**)&v,   g_v);
    cudaGetSymbolAddress((void**)&ath, g_ath); cudaGetSymbolAddress((void**)&atl, g_atl);
    cudaGetSymbolAddress((void**)&x1,  g_x1);
    cudaGetSymbolAddress((void**)&ffh, g_ffh); cudaGetSymbolAddress((void**)&ffl, g_ffl);
    cudaGetSymbolAddress((void**)&wqh, g_wqh); cudaGetSymbolAddress((void**)&wql, g_wql);
    cudaGetSymbolAddress((void**)&wkh, g_wkh); cudaGetSymbolAddress((void**)&wkl, g_wkl);
    cudaGetSymbolAddress((void**)&wvh, g_wvh); cudaGetSymbolAddress((void**)&wvl, g_wvl);
    cudaGetSymbolAddress((void**)&woh, g_woh); cudaGetSymbolAddress((void**)&wol, g_wol);
    cudaGetSymbolAddress((void**)&w1h, g_w1h); cudaGetSymbolAddress((void**)&w1l, g_w1l);
    cudaGetSymbolAddress((void**)&w2h, g_w2h); cudaGetSymbolAddress((void**)&w2l, g_w2l);

    dim3 t256(256);
    dim3 tsq(CC/32, CC/32);

    // weight transpose+split (Wt[N][K] bf16 hi/lo)
    tsplit_k<<<tsq, t256>>>(Wq, wqh, wql, CC, CC);
    tsplit_k<<<tsq, t256>>>(Wk, wkh, wkl, CC, CC);
    tsplit_k<<<tsq, t256>>>(Wv, wvh, wvl, CC, CC);
    tsplit_k<<<tsq, t256>>>(Wo, woh, wol, CC, CC);
    tsplit_k<<<dim3(FF/32, CC/32), t256>>>(W1, w1h, w1l, CC, FF);
    tsplit_k<<<dim3(CC/32, FF/32), t256>>>(W2, w2h, w2l, FF, CC);

    dim3 gSmall(CC/128, MM/128);   // (8, 64)
    dim3 gFF1  (FF/128, MM/128);   // (32, 64)

    // 1. h = LN1(x) -> bf16 hi/lo
    ln_k<<<MM, 256>>>(x, ln1g, ln1b, hh, hl);
    // 2. q,k,v = h @ W{q,k,v}  (fp32 out for attention)
    gemm_mma<0><<<gSmall, t256>>>(hh, hl, wqh, wql, nullptr, nullptr, q, nullptr, nullptr, MM, CC, CC);
    gemm_mma<0><<<gSmall, t256>>>(hh, hl, wkh, wkl, nullptr, nullptr, k, nullptr, nullptr, MM, CC, CC);
    gemm_mma<0><<<gSmall, t256>>>(hh, hl, wvh, wvl, nullptr, nullptr, v, nullptr, nullptr, MM, CC, CC);
    // 3. attention -> bf16 hi/lo
    flash_k<<<dim3(TT/128, BB*HH), 128>>>(q, k, v, ath, atl);
    // 4. x1 = x + at @ Wo + bo (fp32)
    gemm_mma<1><<<gSmall, t256>>>(ath, atl, woh, wol, bo, x, x1, nullptr, nullptr, MM, CC, CC);
    // 5. h = LN2(x1) -> bf16 hi/lo
    ln_k<<<MM, 256>>>(x1, ln2g, ln2b, hh, hl);
    // 6. ff = relu(h @ W1 + b1) -> bf16 hi/lo
    gemm_mma<2><<<gFF1, t256>>>(hh, hl, w1h, w1l, b1, nullptr, nullptr, ffh, ffl, MM, FF, CC);
    // 7. out = x1 + ff @ W2 + b2 (fp32)
    gemm_mma<1><<<gSmall, t256>>>(ffh, ffl, w2h, w2l, b2, x1, out, nullptr, nullptr, MM, CC, FF);
}

// round 9
// speedup vs baseline: 1.0405x; 1.0405x over previous
#include <cuda_runtime.h>
#include <cuda_bf16.h>
#include <cstdint>

// Problem dims (fixed)
#define BB 4
#define TT 2048
#define CC 1024
#define HH 16
#define DD 64
#define FF 4096
#define MM (BB*TT)   // 8192 rows
#define C3 (3*CC)    // fused qkv width

// ===================== PTX helpers (sm_100-safe) ============================
__device__ __forceinline__ uint32_t smem_to_u32(const void* p) {
    uint32_t a;
    asm("{ .reg .u64 t; cvta.to.shared.u64 t, %1; cvt.u32.u64 %0, t; }"
        : "=r"(a) : "l"(p));
    return a;
}
#define CP_ASYNC16(dst, src) \
    asm volatile("cp.async.cg.shared.global [%0], [%1], 16;" :: "r"(dst), "l"(src))
#define CP_COMMIT() asm volatile("cp.async.commit_group;" ::: "memory")
#define CP_WAIT(n)  asm volatile("cp.async.wait_group %0;" :: "n"(n) : "memory")

__device__ __forceinline__ void ldsm4(uint32_t* r, uint32_t addr) {
    asm volatile("ldmatrix.sync.aligned.m8n8.x4.shared.b16 {%0,%1,%2,%3}, [%4];"
        : "=r"(r[0]), "=r"(r[1]), "=r"(r[2]), "=r"(r[3]) : "r"(addr));
}
__device__ __forceinline__ void mma16816(float* c, const uint32_t* a,
                                         uint32_t b0, uint32_t b1) {
    asm volatile(
        "mma.sync.aligned.m16n8k16.row.col.f32.bf16.bf16.f32 "
        "{%0,%1,%2,%3}, {%4,%5,%6,%7}, {%8,%9}, {%0,%1,%2,%3};"
        : "+f"(c[0]), "+f"(c[1]), "+f"(c[2]), "+f"(c[3])
        : "r"(a[0]), "r"(a[1]), "r"(a[2]), "r"(a[3]), "r"(b0), "r"(b1));
}

// ===================== scratch (device globals) =============================
__device__ __nv_bfloat16 g_hh [MM*CC], g_hl [MM*CC];            // LN out hi/lo
__device__ float         g_qkv[(size_t)MM*C3];                  // fused q|k|v fp32
__device__ __nv_bfloat16 g_ath[MM*CC], g_atl[MM*CC];            // attention out hi/lo
__device__ float         g_x1 [MM*CC];
__device__ __nv_bfloat16 g_ffh[(size_t)MM*FF], g_ffl[(size_t)MM*FF];
__device__ __nv_bfloat16 g_wqkvh[(size_t)C3*CC], g_wqkvl[(size_t)C3*CC];
__device__ __nv_bfloat16 g_woh[CC*CC], g_wol[CC*CC];
__device__ __nv_bfloat16 g_w1h[(size_t)CC*FF], g_w1l[(size_t)CC*FF];
__device__ __nv_bfloat16 g_w2h[(size_t)FF*CC], g_w2l[(size_t)FF*CC];

// split fp32 -> (hi, lo) bf16 pair
__device__ __forceinline__ void split2_store(float x0, float x1,
                                             __nv_bfloat16* hp, __nv_bfloat16* lp) {
    __nv_bfloat16 h0 = __float2bfloat16_rn(x0), h1 = __float2bfloat16_rn(x1);
    *(__nv_bfloat162*)hp = __halves2bfloat162(h0, h1);
    float l0 = x0 - __bfloat162float(h0), l1 = x1 - __bfloat162float(h1);
    *(__nv_bfloat162*)lp = __halves2bfloat162(__float2bfloat16_rn(l0),
                                              __float2bfloat16_rn(l1));
}
__device__ __forceinline__ void split4_store(float x0, float x1, float x2, float x3,
                                             __nv_bfloat16* hp, __nv_bfloat16* lp) {
    split2_store(x0, x1, hp, lp);
    split2_store(x2, x3, hp + 2, lp + 2);
}

// ===================== weight transpose + split =============================
// W [K, N] fp32 -> Th/Tl [N, K] bf16 (GEMM B operand is K-major per n-row)
__global__ void __launch_bounds__(256) tsplit_k(const float* __restrict__ W,
                                                __nv_bfloat16* __restrict__ Th,
                                                __nv_bfloat16* __restrict__ Tl,
                                                int K, int N)
{
    __shared__ float t[32][33];
    int n0 = blockIdx.x * 32, k0 = blockIdx.y * 32;
    int tx = threadIdx.x & 31, ty = threadIdx.x >> 5;   // 32 x 8
    #pragma unroll
    for (int i = 0; i < 4; i++)
        t[ty + 8*i][tx] = W[(size_t)(k0 + ty + 8*i) * N + n0 + tx];
    __syncthreads();
    #pragma unroll
    for (int i = 0; i < 4; i++) {
        float v = t[tx][ty + 8*i];
        size_t o = (size_t)(n0 + ty + 8*i) * K + k0 + tx;
        __nv_bfloat16 h = __float2bfloat16_rn(v);
        Th[o] = h;
        Tl[o] = __float2bfloat16_rn(v - __bfloat162float(h));
    }
}

// ===================== LayerNorm -> bf16 hi/lo ==============================
__global__ void __launch_bounds__(256) ln_k(const float* __restrict__ x,
                                            const float* __restrict__ gam,
                                            const float* __restrict__ bet,
                                            __nv_bfloat16* __restrict__ oh,
                                            __nv_bfloat16* __restrict__ ol)
{
    int row = blockIdx.x;
    int tid = threadIdx.x;
    const float4* xr = (const float4*)(x + (size_t)row * CC);
    float4 v = xr[tid];
    float s  = v.x + v.y + v.z + v.w;
    float sq = v.x*v.x + v.y*v.y + v.z*v.z + v.w*v.w;
    #pragma unroll
    for (int o = 16; o > 0; o >>= 1) {
        s  += __shfl_xor_sync(0xffffffffu, s,  o);
        sq += __shfl_xor_sync(0xffffffffu, sq, o);
    }
    __shared__ float rs[8], rq[8];
    int w = tid >> 5, lane = tid & 31;
    if (lane == 0) { rs[w] = s; rq[w] = sq; }
    __syncthreads();
    s = 0.f; sq = 0.f;
    #pragma unroll
    for (int i = 0; i < 8; i++) { s += rs[i]; sq += rq[i]; }
    float mu  = s * (1.f / CC);
    float inv = rsqrtf(sq * (1.f / CC) - mu * mu + 1e-5f);
    float4 g4 = ((const float4*)gam)[tid];
    float4 b4 = ((const float4*)bet)[tid];
    float r0 = (v.x - mu) * inv * g4.x + b4.x;
    float r1 = (v.y - mu) * inv * g4.y + b4.y;
    float r2 = (v.z - mu) * inv * g4.z + b4.z;
    float r3 = (v.w - mu) * inv * g4.w + b4.w;
    size_t base = (size_t)row * CC + tid * 4;
    split4_store(r0, r1, r2, r3, oh + base, ol + base);
}

// ===================== mma.sync GEMM, 3-stage pipeline ======================
// C[M,N] = A[M,K] @ Bt[N,K]^T via 3-term bf16 split (logical K' = 3K):
//   term 0: Ah*Bh, term 1: Al*Bh, term 2: Ah*Bl — fp32 accum.
// 128x128 block, 8 warps (2M x 4N), 64x32 per warp, m16n8k16 frags.
// BK=32 per stage, 3-stage cp.async circular buffer, ONE __syncthreads/stage.
// Smem rows padded to 40 bf16 (5*row+chunk mod 8 permutation: conflict-free).
// EP: 0 = fp32 store; 1 = fp32 (D+bias+res); 2 = bf16 hi/lo split relu(D+bias).
#define STAGES 3
#define ASTRIDE (128*40)     // bf16 elems per stage (10240 B)
template<int EP>
__global__ void __launch_bounds__(256) gemm_mma(
    const __nv_bfloat16* __restrict__ Ah, const __nv_bfloat16* __restrict__ Al,
    const __nv_bfloat16* __restrict__ Bh, const __nv_bfloat16* __restrict__ Bl,
    const float* __restrict__ bias, const float* __restrict__ res,
    float* __restrict__ Cf,
    __nv_bfloat16* __restrict__ Chi, __nv_bfloat16* __restrict__ Clo,
    int M, int N, int K)
{
    extern __shared__ __align__(16) char dsm[];
    __nv_bfloat16* Asb = (__nv_bfloat16*)dsm;                 // [STAGES][128][40]
    __nv_bfloat16* Bsb = Asb + STAGES * ASTRIDE;              // [STAGES][128][40]

    const int tid  = threadIdx.x;
    const int wid  = tid >> 5;
    const int lane = tid & 31;
    const int bm = blockIdx.y * 128, bn = blockIdx.x * 128;
    const int wm = wid & 1;          // 0..1 -> 64-row slice
    const int wn = wid >> 1;         // 0..3 -> 32-col slice

    const int kc = K >> 5;           // 32-wide chunks per term
    const int kt = 3 * kc;           // total stages

    // loader mapping: thread -> (row = tid/2, 16-elem half-row)
    const int lrow = tid >> 1;
    const int lc   = (tid & 1) * 16;

    float acc[4][4][4];
    #pragma unroll
    for (int i = 0; i < 4; i++)
        #pragma unroll
        for (int j = 0; j < 4; j++)
            #pragma unroll
            for (int q = 0; q < 4; q++) acc[i][j][q] = 0.f;

    auto issue = [&](int t) {
        int s = t % STAGES;
        int term = (t >= 2*kc) ? 2 : (t >= kc ? 1 : 0);
        int koff = (t - term * kc) * 32;
        const __nv_bfloat16* pa = (term == 1) ? Al : Ah;
        const __nv_bfloat16* pb = (term == 2) ? Bl : Bh;
        const __nv_bfloat16* ga = pa + (size_t)(bm + lrow) * K + koff + lc;
        const __nv_bfloat16* gb = pb + (size_t)(bn + lrow) * K + koff + lc;
        uint32_t da = smem_to_u32(Asb + s * ASTRIDE + lrow * 40 + lc);
        uint32_t db = smem_to_u32(Bsb + s * ASTRIDE + lrow * 40 + lc);
        CP_ASYNC16(da,      ga);
        CP_ASYNC16(da + 16, ga + 8);
        CP_ASYNC16(db,      gb);
        CP_ASYNC16(db + 16, gb + 8);
    };

    // prologue: fill STAGES-1 stages
    issue(0); CP_COMMIT();
    issue(1); CP_COMMIT();

    for (int t = 0; t < kt; t++) {
        CP_WAIT(STAGES - 2);          // stage t's data resident
        __syncthreads();              // all warps done with stage t-1's buffers
        // prefetch stage t+2 into buffer (t+2)%S = (t-1)%S's slot (safe: read at t-1, done)
        if (t + STAGES - 1 < kt) issue(t + STAGES - 1);
        CP_COMMIT();                  // commit (possibly empty) keeps group count aligned

        const int buf = t % STAGES;
        const __nv_bfloat16* Ast = Asb + buf * ASTRIDE;
        const __nv_bfloat16* Bst = Bsb + buf * ASTRIDE;
        #pragma unroll
        for (int ks = 0; ks < 2; ks++) {
            const int kb = ks * 16 + (lane >> 4) * 8;
            uint32_t a[4][4];
            #pragma unroll
            for (int mf = 0; mf < 4; mf++) {
                uint32_t addr = smem_to_u32(Ast + (wm*64 + mf*16 + (lane & 15)) * 40 + kb);
                ldsm4(a[mf], addr);
            }
            uint32_t b[2][4];
            #pragma unroll
            for (int bf = 0; bf < 2; bf++) {
                uint32_t addr = smem_to_u32(Bst + (wn*32 + bf*16 + (lane & 15)) * 40 + kb);
                ldsm4(b[bf], addr);
            }
            #pragma unroll
            for (int mf = 0; mf < 4; mf++) {
                #pragma unroll
                for (int nf = 0; nf < 4; nf++) {
                    uint32_t b0 = b[nf >> 1][(nf & 1) ? 1 : 0];
                    uint32_t b1 = b[nf >> 1][(nf & 1) ? 3 : 2];
                    mma16816(acc[mf][nf], a[mf], b0, b1);
                }
            }
        }
    }

    // ---- epilogue ----
    const int r0 = bm + wm * 64 + (lane >> 2);
    const int c0 = bn + wn * 32 + (lane & 3) * 2;
    #pragma unroll
    for (int mf = 0; mf < 4; mf++) {
        #pragma unroll
        for (int nf = 0; nf < 4; nf++) {
            int row = r0 + mf * 16;
            int col = c0 + nf * 8;
            #pragma unroll
            for (int half = 0; half < 2; half++) {
                int rr = row + half * 8;
                float v0 = acc[mf][nf][half*2 + 0];
                float v1 = acc[mf][nf][half*2 + 1];
                size_t o = (size_t)rr * N + col;
                if (EP >= 1) {
                    float2 bb = *(const float2*)(bias + col);
                    v0 += bb.x; v1 += bb.y;
                }
                if (EP == 2) {
                    v0 = fmaxf(v0, 0.f); v1 = fmaxf(v1, 0.f);
                    split2_store(v0, v1, Chi + o, Clo + o);
                } else {
                    if (EP == 1) {
                        float2 rv = *(const float2*)(res + o);
                        v0 += rv.x; v1 += rv.y;
                    }
                    *(float2*)(Cf + o) = make_float2(v0, v1);
                }
            }
        }
    }
}

// ===================== Flash attention (causal, fp32 -> bf16 hi/lo out) =====
// Reads fused qkv buffer: q at col 0, k at col CC, v at col 2*CC; row stride C3.
__global__ void __launch_bounds__(128) flash_k(const float* __restrict__ QKV,
                                               __nv_bfloat16* __restrict__ Oh,
                                               __nv_bfloat16* __restrict__ Ol)
{
    __shared__ float q_s[128][68];
    __shared__ float k_s[16][64];
    __shared__ float v_s[16][64];
    int qt  = blockIdx.x;
    int bh  = blockIdx.y;
    int b   = bh >> 4, h = bh & 15;
    int tid = threadIdx.x;

    const float* Qb  = QKV + ((size_t)(b * TT + qt * 128)) * C3 + h * DD;
    const float* Kb0 = QKV + ((size_t)b * TT) * C3 + CC     + h * DD;
    const float* Vb0 = QKV + ((size_t)b * TT) * C3 + 2 * CC + h * DD;

    for (int idx = tid; idx < 128 * 16; idx += 128) {
        int r = idx >> 4, d4 = idx & 15;
        float4 t = *(const float4*)(Qb + (size_t)r * C3 + d4 * 4);
        t.x *= 0.03125f; t.y *= 0.03125f; t.z *= 0.03125f; t.w *= 0.03125f;
        *(float4*)&q_s[r][d4 * 4] = t;
    }

    int qrow = qt * 128 + tid;
    float m = -1e30f, l = 0.f;
    float o[64];
    #pragma unroll
    for (int d = 0; d < 64; d++) o[d] = 0.f;

    int kend = qt * 128 + 128;
    for (int k0 = 0; k0 < kend; k0 += 16) {
        __syncthreads();
        for (int idx = tid; idx < 16 * 16; idx += 128) {
            int r = idx >> 4, d4 = idx & 15;
            *(float4*)&k_s[r][d4*4] = *(const float4*)(Kb0 + (size_t)(k0 + r) * C3 + d4 * 4);
            *(float4*)&v_s[r][d4*4] = *(const float4*)(Vb0 + (size_t)(k0 + r) * C3 + d4 * 4);
        }
        __syncthreads();

        float s[16];
        #pragma unroll
        for (int j = 0; j < 16; j++) s[j] = 0.f;
        #pragma unroll 4
        for (int d4 = 0; d4 < 16; d4++) {
            float4 q4 = *(const float4*)&q_s[tid][d4 * 4];
            #pragma unroll
            for (int j = 0; j < 16; j++) {
                float4 k4 = *(const float4*)&k_s[j][d4 * 4];
                s[j] += q4.x*k4.x + q4.y*k4.y + q4.z*k4.z + q4.w*k4.w;
            }
        }
        if (k0 + 15 > qrow) {
            #pragma unroll
            for (int j = 0; j < 16; j++)
                if (k0 + j > qrow) s[j] = -1e30f;
        }
        float mt = m;
        #pragma unroll
        for (int j = 0; j < 16; j++) mt = fmaxf(mt, s[j]);
        float alpha = __expf(m - mt);
        m = mt;
        l *= alpha;
        #pragma unroll
        for (int d = 0; d < 64; d++) o[d] *= alpha;
        #pragma unroll 4
        for (int j = 0; j < 16; j++) {
            float p = __expf(s[j] - m);
            l += p;
            #pragma unroll
            for (int d4 = 0; d4 < 16; d4++) {
                float4 v4 = *(const float4*)&v_s[j][d4 * 4];
                o[d4*4+0] += p * v4.x;
                o[d4*4+1] += p * v4.y;
                o[d4*4+2] += p * v4.z;
                o[d4*4+3] += p * v4.w;
            }
        }
    }
    float inv = 1.f / l;
    size_t base = ((size_t)(b * TT + qrow)) * CC + h * DD;
    #pragma unroll
    for (int d4 = 0; d4 < 16; d4++) {
        split4_store(o[d4*4+0]*inv, o[d4*4+1]*inv, o[d4*4+2]*inv, o[d4*4+3]*inv,
                     Oh + base + d4*4, Ol + base + d4*4);
    }
}

// ===================== launch ===============================================
extern "C" void kernel_launch(void* const* d_in, const int* in_sizes, int n_in,
                              void* d_out, int out_size)
{
    const float* x     = (const float*)d_in[0];
    const float* Wq    = (const float*)d_in[1];
    const float* Wk    = (const float*)d_in[2];
    const float* Wv    = (const float*)d_in[3];
    const float* Wo    = (const float*)d_in[4];
    const float* bo    = (const float*)d_in[5];
    const float* W1    = (const float*)d_in[6];
    const float* b1    = (const float*)d_in[7];
    const float* W2    = (const float*)d_in[8];
    const float* b2    = (const float*)d_in[9];
    const float* ln1g  = (const float*)d_in[10];
    const float* ln1b  = (const float*)d_in[11];
    const float* ln2g  = (const float*)d_in[12];
    const float* ln2b  = (const float*)d_in[13];
    float* out = (float*)d_out;

    __nv_bfloat16 *hh, *hl, *ath, *atl, *ffh, *ffl;
    __nv_bfloat16 *wqkvh, *wqkvl, *woh, *wol, *w1h, *w1l, *w2h, *w2l;
    float *qkv, *x1;
    cudaGetSymbolAddress((void**)&hh,  g_hh);  cudaGetSymbolAddress((void**)&hl,  g_hl);
    cudaGetSymbolAddress((void**)&qkv, g_qkv);
    cudaGetSymbolAddress((void**)&ath, g_ath); cudaGetSymbolAddress((void**)&atl, g_atl);
    cudaGetSymbolAddress((void**)&x1,  g_x1);
    cudaGetSymbolAddress((void**)&ffh, g_ffh); cudaGetSymbolAddress((void**)&ffl, g_ffl);
    cudaGetSymbolAddress((void**)&wqkvh, g_wqkvh); cudaGetSymbolAddress((void**)&wqkvl, g_wqkvl);
    cudaGetSymbolAddress((void**)&woh, g_woh); cudaGetSymbolAddress((void**)&wol, g_wol);
    cudaGetSymbolAddress((void**)&w1h, g_w1h); cudaGetSymbolAddress((void**)&w1l, g_w1l);
    cudaGetSymbolAddress((void**)&w2h, g_w2h); cudaGetSymbolAddress((void**)&w2l, g_w2l);

    const int SMEM_DYN = STAGES * ASTRIDE * 2 * 2;   // 61,440 B
    static bool attr_done = false;
    if (!attr_done) {
        cudaFuncSetAttribute(gemm_mma<0>, cudaFuncAttributeMaxDynamicSharedMemorySize, SMEM_DYN);
        cudaFuncSetAttribute(gemm_mma<1>, cudaFuncAttributeMaxDynamicSharedMemorySize, SMEM_DYN);
        cudaFuncSetAttribute(gemm_mma<2>, cudaFuncAttributeMaxDynamicSharedMemorySize, SMEM_DYN);
        attr_done = true;
    }

    dim3 t256(256);

    // weight transpose+split: Wq/Wk/Wv -> rows [0,C), [C,2C), [2C,3C) of wqkv
    dim3 tsq(CC/32, CC/32);
    tsplit_k<<<tsq, t256>>>(Wq, wqkvh,                 wqkvl,                 CC, CC);
    tsplit_k<<<tsq, t256>>>(Wk, wqkvh + (size_t)CC*CC, wqkvl + (size_t)CC*CC, CC, CC);
    tsplit_k<<<tsq, t256>>>(Wv, wqkvh + (size_t)2*CC*CC, wqkvl + (size_t)2*CC*CC, CC, CC);
    tsplit_k<<<tsq, t256>>>(Wo, woh, wol, CC, CC);
    tsplit_k<<<dim3(FF/32, CC/32), t256>>>(W1, w1h, w1l, CC, FF);
    tsplit_k<<<dim3(CC/32, FF/32), t256>>>(W2, w2h, w2l, FF, CC);

    dim3 gQKV (C3/128, MM/128);    // (24, 64)
    dim3 gSmall(CC/128, MM/128);   // (8, 64)
    dim3 gFF1  (FF/128, MM/128);   // (32, 64)

    // 1. h = LN1(x) -> bf16 hi/lo
    ln_k<<<MM, 256>>>(x, ln1g, ln1b, hh, hl);
    // 2. qkv = h @ [Wq|Wk|Wv]  (fused, fp32 out)
    gemm_mma<0><<<gQKV, t256, SMEM_DYN>>>(hh, hl, wqkvh, wqkvl, nullptr, nullptr, qkv, nullptr, nullptr, MM, C3, CC);
    // 3. attention -> bf16 hi/lo
    flash_k<<<dim3(TT/128, BB*HH), 128>>>(qkv, ath, atl);
    // 4. x1 = x + at @ Wo + bo (fp32)
    gemm_mma<1><<<gSmall, t256, SMEM_DYN>>>(ath, atl, woh, wol, bo, x, x1, nullptr, nullptr, MM, CC, CC);
    // 5. h = LN2(x1) -> bf16 hi/lo
    ln_k<<<MM, 256>>>(x1, ln2g, ln2b, hh, hl);
    // 6. ff = relu(h @ W1 + b1) -> bf16 hi/lo
    gemm_mma<2><<<gFF1, t256, SMEM_DYN>>>(hh, hl, w1h, w1l, b1, nullptr, nullptr, ffh, ffl, MM, FF, CC);
    // 7. out = x1 + ff @ W2 + b2 (fp32)
    gemm_mma<1><<<gSmall, t256, SMEM_DYN>>>(ffh, ffl, w2h, w2l, b2, x1, out, nullptr, nullptr, MM, CC, FF);
}

// round 10
// speedup vs baseline: 1.4029x; 1.3483x over previous
#include <cuda_runtime.h>
#include <cuda_bf16.h>
#include <cstdint>

// Problem dims (fixed)
#define BB 4
#define TT 2048
#define CC 1024
#define HH 16
#define DD 64
#define FF 4096
#define MM (BB*TT)   // 8192 rows
#define C3 (3*CC)    // fused qkv width

// ===================== PTX helpers (sm_100-safe) ============================
__device__ __forceinline__ uint32_t smem_to_u32(const void* p) {
    uint32_t a;
    asm("{ .reg .u64 t; cvta.to.shared.u64 t, %1; cvt.u32.u64 %0, t; }"
        : "=r"(a) : "l"(p));
    return a;
}
#define CP_ASYNC16(dst, src) \
    asm volatile("cp.async.cg.shared.global [%0], [%1], 16;" :: "r"(dst), "l"(src))
#define CP_COMMIT() asm volatile("cp.async.commit_group;" ::: "memory")
#define CP_WAIT(n)  asm volatile("cp.async.wait_group %0;" :: "n"(n) : "memory")

__device__ __forceinline__ void ldsm4(uint32_t* r, uint32_t addr) {
    asm volatile("ldmatrix.sync.aligned.m8n8.x4.shared.b16 {%0,%1,%2,%3}, [%4];"
        : "=r"(r[0]), "=r"(r[1]), "=r"(r[2]), "=r"(r[3]) : "r"(addr));
}
__device__ __forceinline__ void ldsm4t(uint32_t* r, uint32_t addr) {
    asm volatile("ldmatrix.sync.aligned.m8n8.x4.trans.shared.b16 {%0,%1,%2,%3}, [%4];"
        : "=r"(r[0]), "=r"(r[1]), "=r"(r[2]), "=r"(r[3]) : "r"(addr));
}
__device__ __forceinline__ void mma16816(float* c, const uint32_t* a,
                                         uint32_t b0, uint32_t b1) {
    asm volatile(
        "mma.sync.aligned.m16n8k16.row.col.f32.bf16.bf16.f32 "
        "{%0,%1,%2,%3}, {%4,%5,%6,%7}, {%8,%9}, {%0,%1,%2,%3};"
        : "+f"(c[0]), "+f"(c[1]), "+f"(c[2]), "+f"(c[3])
        : "r"(a[0]), "r"(a[1]), "r"(a[2]), "r"(a[3]), "r"(b0), "r"(b1));
}

// ===================== scratch (device globals) =============================
__device__ __nv_bfloat16 g_hh [MM*CC], g_hl [MM*CC];            // LN out hi/lo
__device__ __nv_bfloat16 g_qkvh[(size_t)MM*C3], g_qkvl[(size_t)MM*C3]; // qkv hi/lo
__device__ __nv_bfloat16 g_ath[MM*CC], g_atl[MM*CC];            // attention out hi/lo
__device__ float         g_x1 [MM*CC];
__device__ __nv_bfloat16 g_ffh[(size_t)MM*FF], g_ffl[(size_t)MM*FF];
__device__ __nv_bfloat16 g_wqkvh[(size_t)C3*CC], g_wqkvl[(size_t)C3*CC];
__device__ __nv_bfloat16 g_woh[CC*CC], g_wol[CC*CC];
__device__ __nv_bfloat16 g_w1h[(size_t)CC*FF], g_w1l[(size_t)CC*FF];
__device__ __nv_bfloat16 g_w2h[(size_t)FF*CC], g_w2l[(size_t)FF*CC];

__device__ __forceinline__ uint32_t pack2bf(float a, float b) {
    __nv_bfloat162 t = __halves2bfloat162(__float2bfloat16_rn(a), __float2bfloat16_rn(b));
    return *(uint32_t*)&t;
}
__device__ __forceinline__ void split2_store(float x0, float x1,
                                             __nv_bfloat16* hp, __nv_bfloat16* lp) {
    __nv_bfloat16 h0 = __float2bfloat16_rn(x0), h1 = __float2bfloat16_rn(x1);
    *(__nv_bfloat162*)hp = __halves2bfloat162(h0, h1);
    float l0 = x0 - __bfloat162float(h0), l1 = x1 - __bfloat162float(h1);
    *(__nv_bfloat162*)lp = __halves2bfloat162(__float2bfloat16_rn(l0),
                                              __float2bfloat16_rn(l1));
}
__device__ __forceinline__ void split4_store(float x0, float x1, float x2, float x3,
                                             __nv_bfloat16* hp, __nv_bfloat16* lp) {
    split2_store(x0, x1, hp, lp);
    split2_store(x2, x3, hp + 2, lp + 2);
}

// ===================== weight transpose + split =============================
__global__ void __launch_bounds__(256) tsplit_k(const float* __restrict__ W,
                                                __nv_bfloat16* __restrict__ Th,
                                                __nv_bfloat16* __restrict__ Tl,
                                                int K, int N)
{
    __shared__ float t[32][33];
    int n0 = blockIdx.x * 32, k0 = blockIdx.y * 32;
    int tx = threadIdx.x & 31, ty = threadIdx.x >> 5;
    #pragma unroll
    for (int i = 0; i < 4; i++)
        t[ty + 8*i][tx] = W[(size_t)(k0 + ty + 8*i) * N + n0 + tx];
    __syncthreads();
    #pragma unroll
    for (int i = 0; i < 4; i++) {
        float v = t[tx][ty + 8*i];
        size_t o = (size_t)(n0 + ty + 8*i) * K + k0 + tx;
        __nv_bfloat16 h = __float2bfloat16_rn(v);
        Th[o] = h;
        Tl[o] = __float2bfloat16_rn(v - __bfloat162float(h));
    }
}

// ===================== LayerNorm -> bf16 hi/lo ==============================
__global__ void __launch_bounds__(256) ln_k(const float* __restrict__ x,
                                            const float* __restrict__ gam,
                                            const float* __restrict__ bet,
                                            __nv_bfloat16* __restrict__ oh,
                                            __nv_bfloat16* __restrict__ ol)
{
    int row = blockIdx.x;
    int tid = threadIdx.x;
    const float4* xr = (const float4*)(x + (size_t)row * CC);
    float4 v = xr[tid];
    float s  = v.x + v.y + v.z + v.w;
    float sq = v.x*v.x + v.y*v.y + v.z*v.z + v.w*v.w;
    #pragma unroll
    for (int o = 16; o > 0; o >>= 1) {
        s  += __shfl_xor_sync(0xffffffffu, s,  o);
        sq += __shfl_xor_sync(0xffffffffu, sq, o);
    }
    __shared__ float rs[8], rq[8];
    int w = tid >> 5, lane = tid & 31;
    if (lane == 0) { rs[w] = s; rq[w] = sq; }
    __syncthreads();
    s = 0.f; sq = 0.f;
    #pragma unroll
    for (int i = 0; i < 8; i++) { s += rs[i]; sq += rq[i]; }
    float mu  = s * (1.f / CC);
    float inv = rsqrtf(sq * (1.f / CC) - mu * mu + 1e-5f);
    float4 g4 = ((const float4*)gam)[tid];
    float4 b4 = ((const float4*)bet)[tid];
    float r0 = (v.x - mu) * inv * g4.x + b4.x;
    float r1 = (v.y - mu) * inv * g4.y + b4.y;
    float r2 = (v.z - mu) * inv * g4.z + b4.z;
    float r3 = (v.w - mu) * inv * g4.w + b4.w;
    size_t base = (size_t)row * CC + tid * 4;
    split4_store(r0, r1, r2, r3, oh + base, ol + base);
}

// ===================== mma.sync GEMM, 4-stage pipeline ======================
// EP: 0 = fp32 store; 1 = fp32 (D+bias+res); 2 = bf16 split relu(D+bias);
//     3 = bf16 split plain store.
#define STAGES 4
#define ASTRIDE (128*40)
template<int EP>
__global__ void __launch_bounds__(256) gemm_mma(
    const __nv_bfloat16* __restrict__ Ah, const __nv_bfloat16* __restrict__ Al,
    const __nv_bfloat16* __restrict__ Bh, const __nv_bfloat16* __restrict__ Bl,
    const float* __restrict__ bias, const float* __restrict__ res,
    float* __restrict__ Cf,
    __nv_bfloat16* __restrict__ Chi, __nv_bfloat16* __restrict__ Clo,
    int M, int N, int K)
{
    extern __shared__ __align__(16) char dsm[];
    __nv_bfloat16* Asb = (__nv_bfloat16*)dsm;
    __nv_bfloat16* Bsb = Asb + STAGES * ASTRIDE;

    const int tid  = threadIdx.x;
    const int wid  = tid >> 5;
    const int lane = tid & 31;
    const int bm = blockIdx.y * 128, bn = blockIdx.x * 128;
    const int wm = wid & 1;
    const int wn = wid >> 1;

    const int kc = K >> 5;
    const int kt = 3 * kc;

    const int lrow = tid >> 1;
    const int lc   = (tid & 1) * 16;

    float acc[4][4][4];
    #pragma unroll
    for (int i = 0; i < 4; i++)
        #pragma unroll
        for (int j = 0; j < 4; j++)
            #pragma unroll
            for (int q = 0; q < 4; q++) acc[i][j][q] = 0.f;

    auto issue = [&](int t) {
        int s = t % STAGES;
        int term = (t >= 2*kc) ? 2 : (t >= kc ? 1 : 0);
        int koff = (t - term * kc) * 32;
        const __nv_bfloat16* pa = (term == 1) ? Al : Ah;
        const __nv_bfloat16* pb = (term == 2) ? Bl : Bh;
        const __nv_bfloat16* ga = pa + (size_t)(bm + lrow) * K + koff + lc;
        const __nv_bfloat16* gb = pb + (size_t)(bn + lrow) * K + koff + lc;
        uint32_t da = smem_to_u32(Asb + s * ASTRIDE + lrow * 40 + lc);
        uint32_t db = smem_to_u32(Bsb + s * ASTRIDE + lrow * 40 + lc);
        CP_ASYNC16(da,      ga);
        CP_ASYNC16(da + 16, ga + 8);
        CP_ASYNC16(db,      gb);
        CP_ASYNC16(db + 16, gb + 8);
    };

    #pragma unroll
    for (int i = 0; i < STAGES - 1; i++) { issue(i); CP_COMMIT(); }

    for (int t = 0; t < kt; t++) {
        CP_WAIT(STAGES - 2);
        __syncthreads();
        if (t + STAGES - 1 < kt) issue(t + STAGES - 1);
        CP_COMMIT();

        const int buf = t % STAGES;
        const __nv_bfloat16* Ast = Asb + buf * ASTRIDE;
        const __nv_bfloat16* Bst = Bsb + buf * ASTRIDE;
        #pragma unroll
        for (int ks = 0; ks < 2; ks++) {
            const int kb = ks * 16 + (lane >> 4) * 8;
            uint32_t a[4][4];
            #pragma unroll
            for (int mf = 0; mf < 4; mf++) {
                uint32_t addr = smem_to_u32(Ast + (wm*64 + mf*16 + (lane & 15)) * 40 + kb);
                ldsm4(a[mf], addr);
            }
            uint32_t b[2][4];
            #pragma unroll
            for (int bf = 0; bf < 2; bf++) {
                uint32_t addr = smem_to_u32(Bst + (wn*32 + bf*16 + (lane & 15)) * 40 + kb);
                ldsm4(b[bf], addr);
            }
            #pragma unroll
            for (int mf = 0; mf < 4; mf++) {
                #pragma unroll
                for (int nf = 0; nf < 4; nf++) {
                    uint32_t b0 = b[nf >> 1][(nf & 1) ? 1 : 0];
                    uint32_t b1 = b[nf >> 1][(nf & 1) ? 3 : 2];
                    mma16816(acc[mf][nf], a[mf], b0, b1);
                }
            }
        }
    }

    const int r0 = bm + wm * 64 + (lane >> 2);
    const int c0 = bn + wn * 32 + (lane & 3) * 2;
    #pragma unroll
    for (int mf = 0; mf < 4; mf++) {
        #pragma unroll
        for (int nf = 0; nf < 4; nf++) {
            int row = r0 + mf * 16;
            int col = c0 + nf * 8;
            #pragma unroll
            for (int half = 0; half < 2; half++) {
                int rr = row + half * 8;
                float v0 = acc[mf][nf][half*2 + 0];
                float v1 = acc[mf][nf][half*2 + 1];
                size_t o = (size_t)rr * N + col;
                if (EP == 1 || EP == 2) {
                    float2 bb = *(const float2*)(bias + col);
                    v0 += bb.x; v1 += bb.y;
                }
                if (EP == 2) {
                    v0 = fmaxf(v0, 0.f); v1 = fmaxf(v1, 0.f);
                }
                if (EP == 2 || EP == 3) {
                    split2_store(v0, v1, Chi + o, Clo + o);
                } else {
                    if (EP == 1) {
                        float2 rv = *(const float2*)(res + o);
                        v0 += rv.x; v1 += rv.y;
                    }
                    *(float2*)(Cf + o) = make_float2(v0, v1);
                }
            }
        }
    }
}

// ===================== Tensorized flash attention ===========================
// 8 warps x m16 q-rows (BM=128), key tiles of 64, split-bf16 3-term for both
// QK^T and PV; fp32 softmax on fragments; double-buffered cp.async KV tiles.
#define KVPAD 72
#define KVARR (64*KVPAD)              // bf16 elems per array (9216B)
#define KVSTAGE (4*KVARR)             // Kh,Kl,Vh,Vl per stage (36864B)
__global__ void __launch_bounds__(256, 1) flash_mma(
    const __nv_bfloat16* __restrict__ QKVh, const __nv_bfloat16* __restrict__ QKVl,
    __nv_bfloat16* __restrict__ Oh, __nv_bfloat16* __restrict__ Ol)
{
    extern __shared__ __align__(16) char dsm[];
    __nv_bfloat16* S0 = (__nv_bfloat16*)dsm;   // 2 stages of KVSTAGE

    const int tid = threadIdx.x, wid = tid >> 5, lane = tid & 31;
    const int qt = (int)gridDim.x - 1 - (int)blockIdx.x;   // heavy tiles first
    const int bh = blockIdx.y;
    const int b = bh >> 4, h = bh & 15;

    const size_t qbase = ((size_t)(b * TT + qt * 128)) * C3 + h * DD;
    const size_t kbase = ((size_t)b * TT) * C3 + CC     + h * DD;
    const size_t vbase = ((size_t)b * TT) * C3 + 2 * CC + h * DD;

    // ---- stage Q (128x64 hi/lo) through smem, extract A-frags ----
    __nv_bfloat16* Qsh = S0;
    __nv_bfloat16* Qsl = S0 + 128 * KVPAD;
    {
        int r = tid >> 1, c0 = (tid & 1) * 32;
        const __nv_bfloat16* gh = QKVh + qbase + (size_t)r * C3 + c0;
        const __nv_bfloat16* gl = QKVl + qbase + (size_t)r * C3 + c0;
        uint32_t dh = smem_to_u32(Qsh + r * KVPAD + c0);
        uint32_t dl = smem_to_u32(Qsl + r * KVPAD + c0);
        #pragma unroll
        for (int i = 0; i < 4; i++) {
            CP_ASYNC16(dh + i*16, gh + i*8);
            CP_ASYNC16(dl + i*16, gl + i*8);
        }
        CP_COMMIT();
        CP_WAIT(0);
    }
    __syncthreads();

    uint32_t qh[4][4], ql[4][4];
    {
        int r = wid * 16 + (lane & 15);
        int cofs = (lane >> 4) * 8;
        #pragma unroll
        for (int kk = 0; kk < 4; kk++) {
            ldsm4(qh[kk], smem_to_u32(Qsh + r * KVPAD + kk * 16 + cofs));
            ldsm4(ql[kk], smem_to_u32(Qsl + r * KVPAD + kk * 16 + cofs));
        }
    }
    __syncthreads();    // everyone has Q frags; smem reusable for KV

    // ---- KV pipeline ----
    const int ntiles = 2 * qt + 2;
    const int aid = tid >> 6;          // 0:Kh 1:Kl 2:Vh 3:Vl
    const int krow = tid & 63;
    auto issueKV = [&](int t) {
        int s = t & 1;
        size_t gofs = (size_t)(t * 64 + krow) * C3;
        const __nv_bfloat16* g =
            (aid == 0) ? QKVh + kbase + gofs :
            (aid == 1) ? QKVl + kbase + gofs :
            (aid == 2) ? QKVh + vbase + gofs :
                         QKVl + vbase + gofs;
        uint32_t d = smem_to_u32(S0 + s * KVSTAGE + aid * KVARR + krow * KVPAD);
        #pragma unroll
        for (int i = 0; i < 8; i++) CP_ASYNC16(d + i*16, g + i*8);
    };
    issueKV(0); CP_COMMIT();

    float oacc[8][4];
    #pragma unroll
    for (int f = 0; f < 8; f++)
        #pragma unroll
        for (int q = 0; q < 4; q++) oacc[f][q] = 0.f;
    float m0 = -1e30f, m1 = -1e30f, l0 = 0.f, l1 = 0.f;

    const int rowg0 = qt * 128 + wid * 16 + (lane >> 2);   // row for regs 0,1
    // rows for regs 2,3 = rowg0 + 8

    for (int t = 0; t < ntiles; t++) {
        CP_WAIT(0);
        __syncthreads();
        if (t + 1 < ntiles) issueKV(t + 1);
        CP_COMMIT();

        const int buf = t & 1;
        const __nv_bfloat16* Kh = S0 + buf * KVSTAGE;
        const __nv_bfloat16* Kl = Kh + KVARR;
        const __nv_bfloat16* Vh = Kh + 2 * KVARR;
        const __nv_bfloat16* Vl = Kh + 3 * KVARR;

        // ---- S = (Qh+Ql)(Kh+Kl)^T, 3 terms ----
        float sacc[8][4];
        #pragma unroll
        for (int f = 0; f < 8; f++)
            #pragma unroll
            for (int q = 0; q < 4; q++) sacc[f][q] = 0.f;

        // K B-frag ldmatrix (non-trans): row = keys, cols = d
        {
            int krw = ((lane >> 4) << 3) + (lane & 7);       // key within 16
            int kcl = ((lane >> 3) & 1) * 8;                 // d sub-block
            #pragma unroll
            for (int kk = 0; kk < 4; kk++) {
                #pragma unroll
                for (int np = 0; np < 4; np++) {
                    uint32_t addr_h = smem_to_u32(Kh + (np*16 + krw) * KVPAD + kk*16 + kcl);
                    uint32_t addr_l = smem_to_u32(Kl + (np*16 + krw) * KVPAD + kk*16 + kcl);
                    uint32_t bh_[4], bl_[4];
                    ldsm4(bh_, addr_h);
                    ldsm4(bl_, addr_l);
                    #pragma unroll
                    for (int j = 0; j < 2; j++) {
                        float* sc = sacc[2*np + j];
                        mma16816(sc, qh[kk], bh_[2*j], bh_[2*j+1]);
                        mma16816(sc, ql[kk], bh_[2*j], bh_[2*j+1]);
                        mma16816(sc, qh[kk], bl_[2*j], bl_[2*j+1]);
                    }
                }
            }
        }

        // ---- scale + causal mask ----
        const int k0 = t * 64;
        #pragma unroll
        for (int f = 0; f < 8; f++)
            #pragma unroll
            for (int q = 0; q < 4; q++) sacc[f][q] *= 0.03125f;
        if (k0 + 63 > rowg0 - (lane >> 2)) {   // diagonal tiles only (tile may exceed some row)
            #pragma unroll
            for (int f = 0; f < 8; f++) {
                int colb = k0 + f * 8 + 2 * (lane & 3);
                #pragma unroll
                for (int q = 0; q < 4; q++) {
                    int col = colb + (q & 1);
                    int row = rowg0 + ((q >> 1) << 3);
                    if (col > row) sacc[f][q] = -1e30f;
                }
            }
        }

        // ---- online softmax on frags ----
        float mx0 = -1e30f, mx1 = -1e30f;
        #pragma unroll
        for (int f = 0; f < 8; f++) {
            mx0 = fmaxf(mx0, fmaxf(sacc[f][0], sacc[f][1]));
            mx1 = fmaxf(mx1, fmaxf(sacc[f][2], sacc[f][3]));
        }
        mx0 = fmaxf(mx0, __shfl_xor_sync(0xffffffffu, mx0, 1));
        mx0 = fmaxf(mx0, __shfl_xor_sync(0xffffffffu, mx0, 2));
        mx1 = fmaxf(mx1, __shfl_xor_sync(0xffffffffu, mx1, 1));
        mx1 = fmaxf(mx1, __shfl_xor_sync(0xffffffffu, mx1, 2));
        float mn0 = fmaxf(m0, mx0), mn1 = fmaxf(m1, mx1);
        float al0 = __expf(m0 - mn0), al1 = __expf(m1 - mn1);
        m0 = mn0; m1 = mn1;
        float sum0 = 0.f, sum1 = 0.f;
        #pragma unroll
        for (int f = 0; f < 8; f++) {
            sacc[f][0] = __expf(sacc[f][0] - mn0); sum0 += sacc[f][0];
            sacc[f][1] = __expf(sacc[f][1] - mn0); sum0 += sacc[f][1];
            sacc[f][2] = __expf(sacc[f][2] - mn1); sum1 += sacc[f][2];
            sacc[f][3] = __expf(sacc[f][3] - mn1); sum1 += sacc[f][3];
        }
        sum0 += __shfl_xor_sync(0xffffffffu, sum0, 1);
        sum0 += __shfl_xor_sync(0xffffffffu, sum0, 2);
        sum1 += __shfl_xor_sync(0xffffffffu, sum1, 1);
        sum1 += __shfl_xor_sync(0xffffffffu, sum1, 2);
        l0 = l0 * al0 + sum0;
        l1 = l1 * al1 + sum1;
        #pragma unroll
        for (int f = 0; f < 8; f++) {
            oacc[f][0] *= al0; oacc[f][1] *= al0;
            oacc[f][2] *= al1; oacc[f][3] *= al1;
        }

        // ---- PV: O += (Ph+Pl)(Vh+Vl), 3 terms ----
        {
            int vrw = ((lane >> 3) & 1) * 8 + (lane & 7);    // key within 16
            int vcl = (lane >> 4) * 8;                       // d sub-block
            #pragma unroll
            for (int kt2 = 0; kt2 < 4; kt2++) {
                // P a-frags (hi, lo) from sacc[2kt2], sacc[2kt2+1]
                uint32_t pha[4], pla[4];
                #pragma unroll
                for (int idx = 0; idx < 4; idx++) {
                    const float* sc = sacc[2*kt2 + (idx >> 1)];
                    float x0 = sc[(idx & 1) * 2 + 0];
                    float x1 = sc[(idx & 1) * 2 + 1];
                    __nv_bfloat16 h0 = __float2bfloat16_rn(x0);
                    __nv_bfloat16 h1 = __float2bfloat16_rn(x1);
                    __nv_bfloat162 hp = __halves2bfloat162(h0, h1);
                    pha[idx] = *(uint32_t*)&hp;
                    __nv_bfloat162 lp = __halves2bfloat162(
                        __float2bfloat16_rn(x0 - __bfloat162float(h0)),
                        __float2bfloat16_rn(x1 - __bfloat162float(h1)));
                    pla[idx] = *(uint32_t*)&lp;
                }
                #pragma unroll
                for (int dp = 0; dp < 4; dp++) {
                    uint32_t addr_h = smem_to_u32(Vh + (kt2*16 + vrw) * KVPAD + dp*16 + vcl);
                    uint32_t addr_l = smem_to_u32(Vl + (kt2*16 + vrw) * KVPAD + dp*16 + vcl);
                    uint32_t bh_[4], bl_[4];
                    ldsm4t(bh_, addr_h);
                    ldsm4t(bl_, addr_l);
                    #pragma unroll
                    for (int j = 0; j < 2; j++) {
                        float* oc = oacc[2*dp + j];
                        mma16816(oc, pha, bh_[2*j], bh_[2*j+1]);
                        mma16816(oc, pla, bh_[2*j], bh_[2*j+1]);
                        mma16816(oc, pha, bl_[2*j], bl_[2*j+1]);
                    }
                }
            }
        }
    }

    // ---- final normalize + split store ----
    float inv0 = 1.f / l0, inv1 = 1.f / l1;
    int row0 = b * TT + rowg0;
    int row1 = row0 + 8;
    int colb = h * DD + 2 * (lane & 3);
    #pragma unroll
    for (int f = 0; f < 8; f++) {
        size_t o0 = (size_t)row0 * CC + colb + f * 8;
        size_t o1 = (size_t)row1 * CC + colb + f * 8;
        split2_store(oacc[f][0] * inv0, oacc[f][1] * inv0, Oh + o0, Ol + o0);
        split2_store(oacc[f][2] * inv1, oacc[f][3] * inv1, Oh + o1, Ol + o1);
    }
}

// ===================== launch ===============================================
extern "C" void kernel_launch(void* const* d_in, const int* in_sizes, int n_in,
                              void* d_out, int out_size)
{
    const float* x     = (const float*)d_in[0];
    const float* Wq    = (const float*)d_in[1];
    const float* Wk    = (const float*)d_in[2];
    const float* Wv    = (const float*)d_in[3];
    const float* Wo    = (const float*)d_in[4];
    const float* bo    = (const float*)d_in[5];
    const float* W1    = (const float*)d_in[6];
    const float* b1    = (const float*)d_in[7];
    const float* W2    = (const float*)d_in[8];
    const float* b2    = (const float*)d_in[9];
    const float* ln1g  = (const float*)d_in[10];
    const float* ln1b  = (const float*)d_in[11];
    const float* ln2g  = (const float*)d_in[12];
    const float* ln2b  = (const float*)d_in[13];
    float* out = (float*)d_out;

    __nv_bfloat16 *hh, *hl, *qkvh, *qkvl, *ath, *atl, *ffh, *ffl;
    __nv_bfloat16 *wqkvh, *wqkvl, *woh, *wol, *w1h, *w1l, *w2h, *w2l;
    float *x1;
    cudaGetSymbolAddress((void**)&hh,   g_hh);   cudaGetSymbolAddress((void**)&hl,   g_hl);
    cudaGetSymbolAddress((void**)&qkvh, g_qkvh); cudaGetSymbolAddress((void**)&qkvl, g_qkvl);
    cudaGetSymbolAddress((void**)&ath,  g_ath);  cudaGetSymbolAddress((void**)&atl,  g_atl);
    cudaGetSymbolAddress((void**)&x1,   g_x1);
    cudaGetSymbolAddress((void**)&ffh,  g_ffh);  cudaGetSymbolAddress((void**)&ffl,  g_ffl);
    cudaGetSymbolAddress((void**)&wqkvh, g_wqkvh); cudaGetSymbolAddress((void**)&wqkvl, g_wqkvl);
    cudaGetSymbolAddress((void**)&woh,  g_woh);  cudaGetSymbolAddress((void**)&wol,  g_wol);
    cudaGetSymbolAddress((void**)&w1h,  g_w1h);  cudaGetSymbolAddress((void**)&w1l,  g_w1l);
    cudaGetSymbolAddress((void**)&w2h,  g_w2h);  cudaGetSymbolAddress((void**)&w2l,  g_w2l);

    const int SMEM_GEMM  = STAGES * ASTRIDE * 2 * 2;   // 81,920 B
    const int SMEM_FLASH = 2 * KVSTAGE * 2;            // 73,728 B? (elems*2B) -> bytes
    static bool attr_done = false;
    if (!attr_done) {
        cudaFuncSetAttribute(gemm_mma<0>, cudaFuncAttributeMaxDynamicSharedMemorySize, SMEM_GEMM);
        cudaFuncSetAttribute(gemm_mma<1>, cudaFuncAttributeMaxDynamicSharedMemorySize, SMEM_GEMM);
        cudaFuncSetAttribute(gemm_mma<2>, cudaFuncAttributeMaxDynamicSharedMemorySize, SMEM_GEMM);
        cudaFuncSetAttribute(gemm_mma<3>, cudaFuncAttributeMaxDynamicSharedMemorySize, SMEM_GEMM);
        cudaFuncSetAttribute(flash_mma, cudaFuncAttributeMaxDynamicSharedMemorySize, SMEM_FLASH);
        attr_done = true;
    }

    dim3 t256(256);
    dim3 tsq(CC/32, CC/32);
    tsplit_k<<<tsq, t256>>>(Wq, wqkvh,                   wqkvl,                   CC, CC);
    tsplit_k<<<tsq, t256>>>(Wk, wqkvh + (size_t)CC*CC,   wqkvl + (size_t)CC*CC,   CC, CC);
    tsplit_k<<<tsq, t256>>>(Wv, wqkvh + (size_t)2*CC*CC, wqkvl + (size_t)2*CC*CC, CC, CC);
    tsplit_k<<<tsq, t256>>>(Wo, woh, wol, CC, CC);
    tsplit_k<<<dim3(FF/32, CC/32), t256>>>(W1, w1h, w1l, CC, FF);
    tsplit_k<<<dim3(CC/32, FF/32), t256>>>(W2, w2h, w2l, FF, CC);

    dim3 gQKV (C3/128, MM/128);
    dim3 gSmall(CC/128, MM/128);
    dim3 gFF1  (FF/128, MM/128);

    // 1. h = LN1(x)
    ln_k<<<MM, 256>>>(x, ln1g, ln1b, hh, hl);
    // 2. qkv = h @ [Wq|Wk|Wv] -> bf16 hi/lo
    gemm_mma<3><<<gQKV, t256, SMEM_GEMM>>>(hh, hl, wqkvh, wqkvl, nullptr, nullptr,
                                           nullptr, qkvh, qkvl, MM, C3, CC);
    // 3. attention (tensorized) -> bf16 hi/lo
    flash_mma<<<dim3(TT/128, BB*HH), 256, SMEM_FLASH>>>(qkvh, qkvl, ath, atl);
    // 4. x1 = x + at @ Wo + bo
    gemm_mma<1><<<gSmall, t256, SMEM_GEMM>>>(ath, atl, woh, wol, bo, x, x1,
                                             nullptr, nullptr, MM, CC, CC);
    // 5. h = LN2(x1)
    ln_k<<<MM, 256>>>(x1, ln2g, ln2b, hh, hl);
    // 6. ff = relu(h @ W1 + b1)
    gemm_mma<2><<<gFF1, t256, SMEM_GEMM>>>(hh, hl, w1h, w1l, b1, nullptr, nullptr,
                                           ffh, ffl, MM, FF, CC);
    // 7. out = x1 + ff @ W2 + b2
    gemm_mma<1><<<gSmall, t256, SMEM_GEMM>>>(ffh, ffl, w2h, w2l, b2, x1, out,
                                             nullptr, nullptr, MM, CC, FF);
}